// round 5
// baseline (speedup 1.0000x reference)
#include <cuda_runtime.h>

#define SEQ    16384
#define CDIM   128
#define KDIM   64
#define BDIM   16
#define NCHUNK 16
#define STILE  64
#define TPB    128
#define NTILE  ((SEQ / NCHUNK) / STILE)   // 16 tiles of 64 s per chunk

// smem layout (floats): cw[64*128] | x_s[128c*64s] | x_t[64s*129] | a_s[64s*66]
// per-k consts (smoothing, s*||cw||^2) live in a_s hole columns 64/65 (row = k)
#define XT_STRIDE 129
#define AS_STRIDE 66
#define SMEM_FLOATS (KDIM*CDIM + CDIM*STILE + STILE*XT_STRIDE + STILE*AS_STRIDE)
#define SMEM_BYTES  (SMEM_FLOATS * 4)     // 115456 B -> 2 CTAs/SM

// deterministic scratch (no atomics)
__device__ float g_epart[(long)NCHUNK * BDIM * KDIM * CDIM];
__device__ float g_Apart[NCHUNK * BDIM * KDIM];
__device__ float g_ecorr[BDIM * KDIM * CDIM];
__device__ float g_gk[KDIM];
__device__ float g_hk[KDIM];
__device__ float g_scale[BDIM * CDIM];

typedef unsigned long long u64;

__device__ __forceinline__ u64 pack2(float lo, float hi) {
    u64 r;
    asm("mov.b64 %0, {%1, %2};" : "=l"(r) : "r"(__float_as_int(lo)), "r"(__float_as_int(hi)));
    return r;
}
__device__ __forceinline__ void unpack2(u64 v, float& lo, float& hi) {
    int a, b;
    asm("mov.b64 {%0, %1}, %2;" : "=r"(a), "=r"(b) : "l"(v));
    lo = __int_as_float(a); hi = __int_as_float(b);
}
__device__ __forceinline__ void fma2(u64& d, u64 a, u64 b) {
    asm("fma.rn.f32x2 %0, %1, %2, %0;" : "+l"(d) : "l"(a), "l"(b));
}
__device__ __forceinline__ unsigned smem_u32(const void* p) {
    unsigned a;
    asm("{ .reg .u64 t; cvta.to.shared.u64 t, %1; cvt.u32.u64 %0, t; }" : "=r"(a) : "l"(p));
    return a;
}
// one LDS.128 -> two u64 operands, no packing MOVs
__device__ __forceinline__ void lds2(u64& a, u64& b, unsigned addr) {
    asm("ld.shared.v2.b64 {%0, %1}, [%2];" : "=l"(a), "=l"(b) : "r"(addr));
}
__device__ __forceinline__ void cp_async16(unsigned dst, const float* src) {
    asm volatile("cp.async.cg.shared.global [%0], [%1], 16;" :: "r"(dst), "l"(src));
}
__device__ __forceinline__ void cp_commit() { asm volatile("cp.async.commit_group;"); }
__device__ __forceinline__ void cp_wait0()  { asm volatile("cp.async.wait_group 0;" ::: "memory"); }

// ---------------------------------------------------------------------------
// Kernel A: cross GEMM + softmax + aggregation GEMM, per (batch, seq-chunk)
// ---------------------------------------------------------------------------
__global__ void __launch_bounds__(TPB, 2) encnet_main(
    const float* __restrict__ x, const float* __restrict__ cw,
    const float* __restrict__ smth)
{
    extern __shared__ float smem[];
    float* cw_s = smem;                         // [64][128]
    float* x_s  = cw_s + KDIM * CDIM;           // [c][s]  128x64 (cp.async staged)
    float* x_t  = x_s + CDIM * STILE;           // [s][c]  64x129
    float* a_s  = x_t + STILE * XT_STRIDE;      // [s][k]  64x66 ; cols 64/65 = consts(k=row)

    const int tid   = threadIdx.x;
    const int chunk = blockIdx.x;
    const int b     = blockIdx.y;

    // codewords -> smem (coalesced)
    {
        const float4* src = reinterpret_cast<const float4*>(cw);
        float4* dst = reinterpret_cast<float4*>(cw_s);
        for (int i = tid; i < KDIM * CDIM / 4; i += TPB) dst[i] = __ldg(src + i);
    }
    // per-k logit constants -> a_s hole columns (row = k): [64]=s_k, [65]=s_k*||cw_k||^2
    if (tid < KDIM) {
        const float4* row = reinterpret_cast<const float4*>(cw + tid * CDIM);
        float c2 = 0.f;
        #pragma unroll
        for (int j = 0; j < CDIM / 4; j++) {
            float4 v = __ldg(row + j);
            c2 += v.x * v.x + v.y * v.y + v.z * v.z + v.w * v.w;
        }
        float s = __ldg(smth + tid);
        a_s[tid * AS_STRIDE + 64] = s;
        a_s[tid * AS_STRIDE + 65] = s * c2;
    }

    const int warp = tid >> 5, lane = tid & 31;
    const int srow = tid & 63, kb = (tid >> 6) * 32;   // cross mapping
    const int kbase = 16 * warp;                       // agg: warp owns 16 k

    const float* xg = x + (long)b * CDIM * SEQ + chunk * (SEQ / NCHUNK);
    const unsigned xs_base = smem_u32(x_s);
    const unsigned cw_base = smem_u32(cw_s);

    // persistent accumulators: eacc[p*4+m] = (e[kbase+2p][lane+32m], e[kbase+2p+1][lane+32m])
    u64 eacc[32];
    #pragma unroll
    for (int i = 0; i < 32; i++) eacc[i] = 0ull;
    float aAcc = 0.f;                                  // tid<64: sum_s a[., tid]

    // prefetch tile 0 into x_s: 2048 x 16B, 16 per thread
    #pragma unroll
    for (int it = 0; it < 16; it++) {
        int idx = tid + it * TPB;                      // 0..2047
        int cc = idx >> 4, seg = idx & 15;
        cp_async16(xs_base + (unsigned)(cc * STILE + seg * 4) * 4u,
                   xg + (long)cc * SEQ + seg * 4);
    }
    cp_commit();

    for (int t = 0; t < NTILE; t++) {
        cp_wait0();
        __syncthreads();   // x_s ready; previous tile's a_s/x_t consumers done

        // ---- cross GEMM + logits: thread = (s, half-of-k) ----
        {
            u64 xr[64];
            float x2 = 0.f;
            #pragma unroll
            for (int j = 0; j < 64; j++) {
                float v0 = x_s[(2 * j) * STILE + srow];
                float v1 = x_s[(2 * j + 1) * STILE + srow];
                if (kb == 0) {                          // transposed copy (scalar stores)
                    x_t[srow * XT_STRIDE + 2 * j]     = v0;
                    x_t[srow * XT_STRIDE + 2 * j + 1] = v1;
                }
                xr[j] = pack2(v0, v1);
                x2 = fmaf(v0, v0, x2);
                x2 = fmaf(v1, v1, x2);
            }
            #pragma unroll 1
            for (int kk = 0; kk < 32; kk += 2) {
                const int k0 = kb + kk;
                const unsigned c0a = cw_base + (unsigned)(k0 * CDIM) * 4u;
                const unsigned c1a = c0a + CDIM * 4u;
                u64 a00 = 0ull, a01 = 0ull, a10 = 0ull, a11 = 0ull;
                #pragma unroll
                for (int j = 0; j < 32; j++) {
                    u64 q0, q1, r0, r1;
                    lds2(q0, q1, c0a + j * 16u);
                    lds2(r0, r1, c1a + j * 16u);
                    fma2(a00, xr[2 * j],     q0);
                    fma2(a10, xr[2 * j],     r0);
                    fma2(a01, xr[2 * j + 1], q1);
                    fma2(a11, xr[2 * j + 1], r1);
                }
                float p0, q0, p1, q1;
                unpack2(a00, p0, q0); unpack2(a01, p1, q1);
                float cr0 = (p0 + q0) + (p1 + q1);
                unpack2(a10, p0, q0); unpack2(a11, p1, q1);
                float cr1 = (p0 + q0) + (p1 + q1);
                float sk0  = a_s[k0 * AS_STRIDE + 64];
                float off0 = a_s[k0 * AS_STRIDE + 65];
                float sk1  = a_s[(k0 + 1) * AS_STRIDE + 64];
                float off1 = a_s[(k0 + 1) * AS_STRIDE + 65];
                // logit = s_k*(x2 - 2*cross) + s_k*cw2
                a_s[srow * AS_STRIDE + k0]     = fmaf(sk0, fmaf(-2.f, cr0, x2), off0);
                a_s[srow * AS_STRIDE + k0 + 1] = fmaf(sk1, fmaf(-2.f, cr1, x2), off1);
            }
        }
        __syncthreads();   // x_s reads done; a_s logits / x_t written

        // prefetch next tile (overlaps softmax + aggregation)
        if (t + 1 < NTILE) {
            const float* xt1 = xg + (t + 1) * STILE;
            #pragma unroll
            for (int it = 0; it < 16; it++) {
                int idx = tid + it * TPB;
                int cc = idx >> 4, seg = idx & 15;
                cp_async16(xs_base + (unsigned)(cc * STILE + seg * 4) * 4u,
                           xt1 + (long)cc * SEQ + seg * 4);
            }
        }
        cp_commit();

        // ---- softmax over k (one thread per s) ----
        if (tid < STILE) {
            float2 l[32];
            float m = -3.4e38f;
            #pragma unroll
            for (int j = 0; j < 32; j++) {
                l[j] = *reinterpret_cast<const float2*>(&a_s[tid * AS_STRIDE + 2 * j]);
                m = fmaxf(m, fmaxf(l[j].x, l[j].y));
            }
            float sum = 0.f;
            #pragma unroll
            for (int j = 0; j < 32; j++) {
                l[j].x = __expf(l[j].x - m);
                l[j].y = __expf(l[j].y - m);
                sum += l[j].x + l[j].y;
            }
            float inv = 1.f / sum;
            #pragma unroll
            for (int j = 0; j < 32; j++) {
                l[j].x *= inv; l[j].y *= inv;
                *reinterpret_cast<float2*>(&a_s[tid * AS_STRIDE + 2 * j]) = l[j];
            }
        }
        __syncthreads();

        // ---- aggregation GEMM: warp owns 16 k (broadcast a), lane owns 4 strided c ----
        {
            #pragma unroll 2
            for (int s = 0; s < STILE; s++) {
                const u64* ar = reinterpret_cast<const u64*>(a_s + s * AS_STRIDE + kbase);
                u64 ap0 = ar[0], ap1 = ar[1], ap2 = ar[2], ap3 = ar[3];
                u64 ap4 = ar[4], ap5 = ar[5], ap6 = ar[6], ap7 = ar[7];
                const float* xrow = x_t + s * XT_STRIDE + lane;
                u64 xs0 = pack2(xrow[0],  xrow[0]);
                u64 xs1 = pack2(xrow[32], xrow[32]);
                u64 xs2 = pack2(xrow[64], xrow[64]);
                u64 xs3 = pack2(xrow[96], xrow[96]);
                fma2(eacc[0],  ap0, xs0); fma2(eacc[1],  ap0, xs1);
                fma2(eacc[2],  ap0, xs2); fma2(eacc[3],  ap0, xs3);
                fma2(eacc[4],  ap1, xs0); fma2(eacc[5],  ap1, xs1);
                fma2(eacc[6],  ap1, xs2); fma2(eacc[7],  ap1, xs3);
                fma2(eacc[8],  ap2, xs0); fma2(eacc[9],  ap2, xs1);
                fma2(eacc[10], ap2, xs2); fma2(eacc[11], ap2, xs3);
                fma2(eacc[12], ap3, xs0); fma2(eacc[13], ap3, xs1);
                fma2(eacc[14], ap3, xs2); fma2(eacc[15], ap3, xs3);
                fma2(eacc[16], ap4, xs0); fma2(eacc[17], ap4, xs1);
                fma2(eacc[18], ap4, xs2); fma2(eacc[19], ap4, xs3);
                fma2(eacc[20], ap5, xs0); fma2(eacc[21], ap5, xs1);
                fma2(eacc[22], ap5, xs2); fma2(eacc[23], ap5, xs3);
                fma2(eacc[24], ap6, xs0); fma2(eacc[25], ap6, xs1);
                fma2(eacc[26], ap6, xs2); fma2(eacc[27], ap6, xs3);
                fma2(eacc[28], ap7, xs0); fma2(eacc[29], ap7, xs1);
                fma2(eacc[30], ap7, xs2); fma2(eacc[31], ap7, xs3);
            }
        }

        // ---- per-k sum of a over this tile (conflict-free) ----
        if (tid < KDIM) {
            #pragma unroll 8
            for (int s = 0; s < STILE; s++) aAcc += a_s[s * AS_STRIDE + tid];
        }
        __syncthreads();   // orders a_s/x_t rewrite by next tile's cross
    }

    // ---- write deterministic chunk partials ----
    {
        float* ep = g_epart + ((long)(chunk * BDIM + b) * KDIM) * CDIM;
        #pragma unroll
        for (int p = 0; p < 8; p++) {
            #pragma unroll
            for (int m = 0; m < 4; m++) {
                float lo, hi;
                unpack2(eacc[p * 4 + m], lo, hi);
                ep[(kbase + 2 * p)     * CDIM + lane + 32 * m] = lo;
                ep[(kbase + 2 * p + 1) * CDIM + lane + 32 * m] = hi;
            }
        }
        if (tid < KDIM) g_Apart[(chunk * BDIM + b) * KDIM + tid] = aAcc;
    }
}

// ---------------------------------------------------------------------------
// Kernel B: reduce chunk partials, subtract A*cw, BN batch stats per k
// ---------------------------------------------------------------------------
__global__ void encnet_stats(const float* __restrict__ cw,
                             const float* __restrict__ bnw,
                             const float* __restrict__ bnb)
{
    const int k = blockIdx.x, tid = threadIdx.x;   // 256 threads
    __shared__ float Ab[BDIM];
    __shared__ float red[256];

    if (tid < BDIM) {
        float a = 0.f;
        #pragma unroll
        for (int ch = 0; ch < NCHUNK; ch++) a += g_Apart[(ch * BDIM + tid) * KDIM + k];
        Ab[tid] = a;
    }
    __syncthreads();

    float sum = 0.f, ss = 0.f;
    for (int i = tid; i < BDIM * CDIM; i += 256) {
        int bb = i >> 7, c = i & 127;
        float v = 0.f;
        #pragma unroll
        for (int ch = 0; ch < NCHUNK; ch++)
            v += g_epart[(((long)ch * BDIM + bb) * KDIM + k) * CDIM + c];
        v -= Ab[bb] * __ldg(cw + k * CDIM + c);
        g_ecorr[(bb * KDIM + k) * CDIM + c] = v;
        sum += v;
        ss = fmaf(v, v, ss);
    }
    red[tid] = sum; __syncthreads();
    for (int o = 128; o > 0; o >>= 1) { if (tid < o) red[tid] += red[tid + o]; __syncthreads(); }
    float tsum = red[0]; __syncthreads();
    red[tid] = ss; __syncthreads();
    for (int o = 128; o > 0; o >>= 1) { if (tid < o) red[tid] += red[tid + o]; __syncthreads(); }
    if (tid == 0) {
        const float n = (float)(BDIM * CDIM);
        float mean = tsum / n;
        float var = red[0] / n - mean * mean;
        float rstd = rsqrtf(var + 1e-5f);
        float g = rstd * __ldg(bnw + k);
        g_gk[k] = g;
        g_hk[k] = __ldg(bnb + k) - mean * g;
    }
}

// ---------------------------------------------------------------------------
// Kernel C: e_norm (mean of relu over k) + FC + sigmoid -> per-(b,c) scale
// ---------------------------------------------------------------------------
__global__ void encnet_fc(const float* __restrict__ fcw, const float* __restrict__ fcb)
{
    const int b = blockIdx.x, tid = threadIdx.x;   // 128 threads
    __shared__ float en[CDIM];
    float acc = 0.f;
    #pragma unroll 4
    for (int k = 0; k < KDIM; k++) {
        float v = g_ecorr[(b * KDIM + k) * CDIM + tid];
        acc += fmaxf(fmaf(v, g_gk[k], g_hk[k]), 0.f);
    }
    en[tid] = acc * (1.f / (float)KDIM);
    __syncthreads();

    float lg = __ldg(fcb + tid);
    const float* wr = fcw + tid * CDIM;
    #pragma unroll 4
    for (int c2 = 0; c2 < CDIM; c2++) lg = fmaf(en[c2], __ldg(wr + c2), lg);
    g_scale[b * CDIM + tid] = 1.f / (1.f + __expf(-lg));
}

// ---------------------------------------------------------------------------
// Kernel D: out = x * scale  (memory bound)
// ---------------------------------------------------------------------------
__global__ void encnet_scale(const float4* __restrict__ x4, float4* __restrict__ out4)
{
    const int total = (BDIM * CDIM * SEQ) / 4;
    for (int i = blockIdx.x * blockDim.x + threadIdx.x; i < total;
         i += gridDim.x * blockDim.x) {
        float s = __ldg(&g_scale[i >> 12]);
        float4 v = __ldg(x4 + i);
        v.x *= s; v.y *= s; v.z *= s; v.w *= s;
        out4[i] = v;
    }
}

// ---------------------------------------------------------------------------
extern "C" void kernel_launch(void* const* d_in, const int* in_sizes, int n_in,
                              void* d_out, int out_size)
{
    const float* x    = (const float*)d_in[0];
    const float* cw   = (const float*)d_in[1];
    const float* smth = (const float*)d_in[2];
    const float* bnw  = (const float*)d_in[3];
    const float* bnb  = (const float*)d_in[4];
    const float* fcw  = (const float*)d_in[5];
    const float* fcb  = (const float*)d_in[6];
    float* out = (float*)d_out;

    cudaFuncSetAttribute(encnet_main, cudaFuncAttributeMaxDynamicSharedMemorySize, SMEM_BYTES);

    encnet_main <<<dim3(NCHUNK, BDIM), TPB, SMEM_BYTES>>>(x, cw, smth);
    encnet_stats<<<KDIM, 256>>>(cw, bnw, bnb);
    encnet_fc   <<<BDIM, CDIM>>>(fcw, fcb);
    encnet_scale<<<4096, 256>>>((const float4*)x, (float4*)out);
}

// round 6
// speedup vs baseline: 1.0025x; 1.0025x over previous
#include <cuda_runtime.h>

#define SEQ    16384
#define CDIM   128
#define KDIM   64
#define BDIM   16
#define NCHUNK 16
#define STILE  64
#define TPB    128
#define NTILE  ((SEQ / NCHUNK) / STILE)   // 16 tiles of 64 s per chunk

// smem layout (floats): cw[64*128] | x_s[128c*64s] | x_t[64s*129] | a_s[64s*66]
// per-k consts (smoothing, s*||cw||^2) live in a_s hole columns 64/65 (row = k)
#define XT_STRIDE 129
#define AS_STRIDE 66
#define SMEM_FLOATS (KDIM*CDIM + CDIM*STILE + STILE*XT_STRIDE + STILE*AS_STRIDE)
#define SMEM_BYTES  (SMEM_FLOATS * 4)     // 115456 B -> 2 CTAs/SM

// deterministic scratch (no atomics)
__device__ float g_epart[(long)NCHUNK * BDIM * KDIM * CDIM];
__device__ float g_Apart[NCHUNK * BDIM * KDIM];
__device__ float g_ecorr[BDIM * KDIM * CDIM];
__device__ float g_gk[KDIM];
__device__ float g_hk[KDIM];
__device__ float g_scale[BDIM * CDIM];

typedef unsigned long long u64;

__device__ __forceinline__ u64 pack2(float lo, float hi) {
    u64 r;
    asm("mov.b64 %0, {%1, %2};" : "=l"(r) : "r"(__float_as_int(lo)), "r"(__float_as_int(hi)));
    return r;
}
__device__ __forceinline__ void unpack2(u64 v, float& lo, float& hi) {
    int a, b;
    asm("mov.b64 {%0, %1}, %2;" : "=r"(a), "=r"(b) : "l"(v));
    lo = __int_as_float(a); hi = __int_as_float(b);
}
__device__ __forceinline__ void fma2(u64& d, u64 a, u64 b) {
    asm("fma.rn.f32x2 %0, %1, %2, %0;" : "+l"(d) : "l"(a), "l"(b));
}
__device__ __forceinline__ unsigned smem_u32(const void* p) {
    unsigned a;
    asm("{ .reg .u64 t; cvta.to.shared.u64 t, %1; cvt.u32.u64 %0, t; }" : "=r"(a) : "l"(p));
    return a;
}
// one LDS.128 -> two u64 operands, no packing MOVs
__device__ __forceinline__ void lds2(u64& a, u64& b, unsigned addr) {
    asm("ld.shared.v2.b64 {%0, %1}, [%2];" : "=l"(a), "=l"(b) : "r"(addr));
}
__device__ __forceinline__ void cp_async16(unsigned dst, const float* src) {
    asm volatile("cp.async.cg.shared.global [%0], [%1], 16;" :: "r"(dst), "l"(src));
}
__device__ __forceinline__ void cp_commit() { asm volatile("cp.async.commit_group;"); }
__device__ __forceinline__ void cp_wait0()  { asm volatile("cp.async.wait_group 0;" ::: "memory"); }

// ---------------------------------------------------------------------------
// Kernel A: cross GEMM + softmax + aggregation GEMM, per (batch, seq-chunk)
// ---------------------------------------------------------------------------
__global__ void __launch_bounds__(TPB, 2) encnet_main(
    const float* __restrict__ x, const float* __restrict__ cw,
    const float* __restrict__ smth)
{
    extern __shared__ float smem[];
    float* cw_s = smem;                         // [64][128]
    float* x_s  = cw_s + KDIM * CDIM;           // [c][s]  128x64 (cp.async staged)
    float* x_t  = x_s + CDIM * STILE;           // [s][c]  64x129
    float* a_s  = x_t + STILE * XT_STRIDE;      // [s][k]  64x66 ; cols 64/65 = consts(k=row)

    const int tid   = threadIdx.x;
    const int chunk = blockIdx.x;
    const int b     = blockIdx.y;

    // codewords -> smem (coalesced)
    {
        const float4* src = reinterpret_cast<const float4*>(cw);
        float4* dst = reinterpret_cast<float4*>(cw_s);
        for (int i = tid; i < KDIM * CDIM / 4; i += TPB) dst[i] = __ldg(src + i);
    }
    // per-k logit constants -> a_s hole columns (row = k): [64]=s_k, [65]=s_k*||cw_k||^2
    if (tid < KDIM) {
        const float4* row = reinterpret_cast<const float4*>(cw + tid * CDIM);
        float c2 = 0.f;
        #pragma unroll
        for (int j = 0; j < CDIM / 4; j++) {
            float4 v = __ldg(row + j);
            c2 += v.x * v.x + v.y * v.y + v.z * v.z + v.w * v.w;
        }
        float s = __ldg(smth + tid);
        a_s[tid * AS_STRIDE + 64] = s;
        a_s[tid * AS_STRIDE + 65] = s * c2;
    }

    const int warp = tid >> 5, lane = tid & 31;
    const int srow = tid & 63, kb = (tid >> 6) * 32;   // cross mapping
    const int kbase = 16 * warp;                       // agg: warp owns 16 k

    const float* xg = x + (long)b * CDIM * SEQ + chunk * (SEQ / NCHUNK);
    const unsigned xs_base = smem_u32(x_s);
    const unsigned cw_base = smem_u32(cw_s);

    // persistent accumulators: eacc[p*4+m] = (e[kbase+2p][lane+32m], e[kbase+2p+1][lane+32m])
    u64 eacc[32];
    #pragma unroll
    for (int i = 0; i < 32; i++) eacc[i] = 0ull;
    float aAcc = 0.f;                                  // tid<64: sum_s a[., tid]

    // prefetch tile 0 into x_s: 2048 x 16B, 16 per thread
    #pragma unroll
    for (int it = 0; it < 16; it++) {
        int idx = tid + it * TPB;                      // 0..2047
        int cc = idx >> 4, seg = idx & 15;
        cp_async16(xs_base + (unsigned)(cc * STILE + seg * 4) * 4u,
                   xg + (long)cc * SEQ + seg * 4);
    }
    cp_commit();

    for (int t = 0; t < NTILE; t++) {
        cp_wait0();
        __syncthreads();   // x_s ready; previous tile's a_s/x_t consumers done

        // ---- cross GEMM + logits: thread = (s, half-of-k) ----
        {
            u64 xr[64];
            float x2 = 0.f;
            #pragma unroll
            for (int j = 0; j < 64; j++) {
                float v0 = x_s[(2 * j) * STILE + srow];
                float v1 = x_s[(2 * j + 1) * STILE + srow];
                if (kb == 0) {                          // transposed copy (scalar stores)
                    x_t[srow * XT_STRIDE + 2 * j]     = v0;
                    x_t[srow * XT_STRIDE + 2 * j + 1] = v1;
                }
                xr[j] = pack2(v0, v1);
                x2 = fmaf(v0, v0, x2);
                x2 = fmaf(v1, v1, x2);
            }
            #pragma unroll 1
            for (int kk = 0; kk < 32; kk += 2) {
                const int k0 = kb + kk;
                const unsigned c0a = cw_base + (unsigned)(k0 * CDIM) * 4u;
                const unsigned c1a = c0a + CDIM * 4u;
                u64 a00 = 0ull, a01 = 0ull, a10 = 0ull, a11 = 0ull;
                #pragma unroll
                for (int j = 0; j < 32; j++) {
                    u64 q0, q1, r0, r1;
                    lds2(q0, q1, c0a + j * 16u);
                    lds2(r0, r1, c1a + j * 16u);
                    fma2(a00, xr[2 * j],     q0);
                    fma2(a10, xr[2 * j],     r0);
                    fma2(a01, xr[2 * j + 1], q1);
                    fma2(a11, xr[2 * j + 1], r1);
                }
                float p0, q0, p1, q1;
                unpack2(a00, p0, q0); unpack2(a01, p1, q1);
                float cr0 = (p0 + q0) + (p1 + q1);
                unpack2(a10, p0, q0); unpack2(a11, p1, q1);
                float cr1 = (p0 + q0) + (p1 + q1);
                float sk0  = a_s[k0 * AS_STRIDE + 64];
                float off0 = a_s[k0 * AS_STRIDE + 65];
                float sk1  = a_s[(k0 + 1) * AS_STRIDE + 64];
                float off1 = a_s[(k0 + 1) * AS_STRIDE + 65];
                // logit = s_k*(x2 - 2*cross) + s_k*cw2
                a_s[srow * AS_STRIDE + k0]     = fmaf(sk0, fmaf(-2.f, cr0, x2), off0);
                a_s[srow * AS_STRIDE + k0 + 1] = fmaf(sk1, fmaf(-2.f, cr1, x2), off1);
            }
        }
        __syncthreads();   // x_s reads done; a_s logits / x_t written

        // prefetch next tile (overlaps softmax + aggregation)
        if (t + 1 < NTILE) {
            const float* xt1 = xg + (t + 1) * STILE;
            #pragma unroll
            for (int it = 0; it < 16; it++) {
                int idx = tid + it * TPB;
                int cc = idx >> 4, seg = idx & 15;
                cp_async16(xs_base + (unsigned)(cc * STILE + seg * 4) * 4u,
                           xt1 + (long)cc * SEQ + seg * 4);
            }
        }
        cp_commit();

        // ---- softmax over k (one thread per s) ----
        if (tid < STILE) {
            float2 l[32];
            float m = -3.4e38f;
            #pragma unroll
            for (int j = 0; j < 32; j++) {
                l[j] = *reinterpret_cast<const float2*>(&a_s[tid * AS_STRIDE + 2 * j]);
                m = fmaxf(m, fmaxf(l[j].x, l[j].y));
            }
            float sum = 0.f;
            #pragma unroll
            for (int j = 0; j < 32; j++) {
                l[j].x = __expf(l[j].x - m);
                l[j].y = __expf(l[j].y - m);
                sum += l[j].x + l[j].y;
            }
            float inv = 1.f / sum;
            #pragma unroll
            for (int j = 0; j < 32; j++) {
                l[j].x *= inv; l[j].y *= inv;
                *reinterpret_cast<float2*>(&a_s[tid * AS_STRIDE + 2 * j]) = l[j];
            }
        }
        __syncthreads();

        // ---- aggregation GEMM: warp owns 16 k (broadcast a), lane owns 4 strided c ----
        {
            #pragma unroll 2
            for (int s = 0; s < STILE; s++) {
                const u64* ar = reinterpret_cast<const u64*>(a_s + s * AS_STRIDE + kbase);
                u64 ap0 = ar[0], ap1 = ar[1], ap2 = ar[2], ap3 = ar[3];
                u64 ap4 = ar[4], ap5 = ar[5], ap6 = ar[6], ap7 = ar[7];
                const float* xrow = x_t + s * XT_STRIDE + lane;
                u64 xs0 = pack2(xrow[0],  xrow[0]);
                u64 xs1 = pack2(xrow[32], xrow[32]);
                u64 xs2 = pack2(xrow[64], xrow[64]);
                u64 xs3 = pack2(xrow[96], xrow[96]);
                fma2(eacc[0],  ap0, xs0); fma2(eacc[1],  ap0, xs1);
                fma2(eacc[2],  ap0, xs2); fma2(eacc[3],  ap0, xs3);
                fma2(eacc[4],  ap1, xs0); fma2(eacc[5],  ap1, xs1);
                fma2(eacc[6],  ap1, xs2); fma2(eacc[7],  ap1, xs3);
                fma2(eacc[8],  ap2, xs0); fma2(eacc[9],  ap2, xs1);
                fma2(eacc[10], ap2, xs2); fma2(eacc[11], ap2, xs3);
                fma2(eacc[12], ap3, xs0); fma2(eacc[13], ap3, xs1);
                fma2(eacc[14], ap3, xs2); fma2(eacc[15], ap3, xs3);
                fma2(eacc[16], ap4, xs0); fma2(eacc[17], ap4, xs1);
                fma2(eacc[18], ap4, xs2); fma2(eacc[19], ap4, xs3);
                fma2(eacc[20], ap5, xs0); fma2(eacc[21], ap5, xs1);
                fma2(eacc[22], ap5, xs2); fma2(eacc[23], ap5, xs3);
                fma2(eacc[24], ap6, xs0); fma2(eacc[25], ap6, xs1);
                fma2(eacc[26], ap6, xs2); fma2(eacc[27], ap6, xs3);
                fma2(eacc[28], ap7, xs0); fma2(eacc[29], ap7, xs1);
                fma2(eacc[30], ap7, xs2); fma2(eacc[31], ap7, xs3);
            }
        }

        // ---- per-k sum of a over this tile (conflict-free) ----
        if (tid < KDIM) {
            #pragma unroll 8
            for (int s = 0; s < STILE; s++) aAcc += a_s[s * AS_STRIDE + tid];
        }
        __syncthreads();   // orders a_s/x_t rewrite by next tile's cross
    }

    // ---- write deterministic chunk partials ----
    {
        float* ep = g_epart + ((long)(chunk * BDIM + b) * KDIM) * CDIM;
        #pragma unroll
        for (int p = 0; p < 8; p++) {
            #pragma unroll
            for (int m = 0; m < 4; m++) {
                float lo, hi;
                unpack2(eacc[p * 4 + m], lo, hi);
                ep[(kbase + 2 * p)     * CDIM + lane + 32 * m] = lo;
                ep[(kbase + 2 * p + 1) * CDIM + lane + 32 * m] = hi;
            }
        }
        if (tid < KDIM) g_Apart[(chunk * BDIM + b) * KDIM + tid] = aAcc;
    }
}

// ---------------------------------------------------------------------------
// Kernel B: reduce chunk partials, subtract A*cw, BN batch stats per k
// ---------------------------------------------------------------------------
__global__ void encnet_stats(const float* __restrict__ cw,
                             const float* __restrict__ bnw,
                             const float* __restrict__ bnb)
{
    const int k = blockIdx.x, tid = threadIdx.x;   // 256 threads
    __shared__ float Ab[BDIM];
    __shared__ float red[256];

    if (tid < BDIM) {
        float a = 0.f;
        #pragma unroll
        for (int ch = 0; ch < NCHUNK; ch++) a += g_Apart[(ch * BDIM + tid) * KDIM + k];
        Ab[tid] = a;
    }
    __syncthreads();

    float sum = 0.f, ss = 0.f;
    for (int i = tid; i < BDIM * CDIM; i += 256) {
        int bb = i >> 7, c = i & 127;
        float v = 0.f;
        #pragma unroll
        for (int ch = 0; ch < NCHUNK; ch++)
            v += g_epart[(((long)ch * BDIM + bb) * KDIM + k) * CDIM + c];
        v -= Ab[bb] * __ldg(cw + k * CDIM + c);
        g_ecorr[(bb * KDIM + k) * CDIM + c] = v;
        sum += v;
        ss = fmaf(v, v, ss);
    }
    red[tid] = sum; __syncthreads();
    for (int o = 128; o > 0; o >>= 1) { if (tid < o) red[tid] += red[tid + o]; __syncthreads(); }
    float tsum = red[0]; __syncthreads();
    red[tid] = ss; __syncthreads();
    for (int o = 128; o > 0; o >>= 1) { if (tid < o) red[tid] += red[tid + o]; __syncthreads(); }
    if (tid == 0) {
        const float n = (float)(BDIM * CDIM);
        float mean = tsum / n;
        float var = red[0] / n - mean * mean;
        float rstd = rsqrtf(var + 1e-5f);
        float g = rstd * __ldg(bnw + k);
        g_gk[k] = g;
        g_hk[k] = __ldg(bnb + k) - mean * g;
    }
}

// ---------------------------------------------------------------------------
// Kernel C: e_norm (mean of relu over k) + FC + sigmoid -> per-(b,c) scale
// ---------------------------------------------------------------------------
__global__ void encnet_fc(const float* __restrict__ fcw, const float* __restrict__ fcb)
{
    const int b = blockIdx.x, tid = threadIdx.x;   // 128 threads
    __shared__ float en[CDIM];
    float acc = 0.f;
    #pragma unroll 4
    for (int k = 0; k < KDIM; k++) {
        float v = g_ecorr[(b * KDIM + k) * CDIM + tid];
        acc += fmaxf(fmaf(v, g_gk[k], g_hk[k]), 0.f);
    }
    en[tid] = acc * (1.f / (float)KDIM);
    __syncthreads();

    float lg = __ldg(fcb + tid);
    const float* wr = fcw + tid * CDIM;
    #pragma unroll 4
    for (int c2 = 0; c2 < CDIM; c2++) lg = fmaf(en[c2], __ldg(wr + c2), lg);
    g_scale[b * CDIM + tid] = 1.f / (1.f + __expf(-lg));
}

// ---------------------------------------------------------------------------
// Kernel D: out = x * scale  (memory bound)
// ---------------------------------------------------------------------------
__global__ void encnet_scale(const float4* __restrict__ x4, float4* __restrict__ out4)
{
    const int total = (BDIM * CDIM * SEQ) / 4;
    for (int i = blockIdx.x * blockDim.x + threadIdx.x; i < total;
         i += gridDim.x * blockDim.x) {
        float s = __ldg(&g_scale[i >> 12]);
        float4 v = __ldg(x4 + i);
        v.x *= s; v.y *= s; v.z *= s; v.w *= s;
        out4[i] = v;
    }
}

// ---------------------------------------------------------------------------
extern "C" void kernel_launch(void* const* d_in, const int* in_sizes, int n_in,
                              void* d_out, int out_size)
{
    const float* x    = (const float*)d_in[0];
    const float* cw   = (const float*)d_in[1];
    const float* smth = (const float*)d_in[2];
    const float* bnw  = (const float*)d_in[3];
    const float* bnb  = (const float*)d_in[4];
    const float* fcw  = (const float*)d_in[5];
    const float* fcb  = (const float*)d_in[6];
    float* out = (float*)d_out;

    cudaFuncSetAttribute(encnet_main, cudaFuncAttributeMaxDynamicSharedMemorySize, SMEM_BYTES);

    encnet_main <<<dim3(NCHUNK, BDIM), TPB, SMEM_BYTES>>>(x, cw, smth);
    encnet_stats<<<KDIM, 256>>>(cw, bnw, bnb);
    encnet_fc   <<<BDIM, CDIM>>>(fcw, fcb);
    encnet_scale<<<4096, 256>>>((const float4*)x, (float4*)out);
}

// round 8
// speedup vs baseline: 2.7320x; 2.7253x over previous
#include <cuda_runtime.h>
#include <cuda_bf16.h>
#include <cstdint>

#define SEQ    16384
#define CDIM   128
#define KDIM   64
#define BDIM   16
#define NCHUNK 8
#define STILE  128
#define TPB    256
#define NTILE  ((SEQ / NCHUNK) / STILE)   // 16

#define XT_ST  136       // bf16 elems per row -> 272B rows (ldmatrix conflict-free)
#define XS_ST  132       // fp32 staging row stride

// smem byte offsets
#define SM_X2   0                              // x2[128] f32
#define SM_C4   512                            // float4[64] per-k consts
#define SM_XTH  2048                           // X^T[c][s] hi bf16 128x136 (34816)
#define SM_XTL  (SM_XTH + 128*XT_ST*2)         // lo (34816)
#define SM_CW   (SM_XTL + 128*XT_ST*2)         // CW[k][c] bf16 64x136 (17408)
#define SM_AT   (SM_CW  + 64*XT_ST*2)          // a^T[k][s] bf16 64x136 (17408)
#define SM_XS   (SM_AT  + 64*XT_ST*2)          // fp32 staging [c][s] 128x132 (67584)
#define SMEM_BYTES (SM_XS + 128*XS_ST*4)       // 174080

// deterministic scratch
__device__ float g_epart[(long)NCHUNK * BDIM * KDIM * CDIM];
__device__ float g_Apart[NCHUNK * BDIM * KDIM];
__device__ float g_ecorr[BDIM * KDIM * CDIM];
__device__ float g_gk[KDIM];
__device__ float g_hk[KDIM];
__device__ float g_scale[BDIM * CDIM];

__device__ __forceinline__ uint32_t smem_u32(const void* p) {
    uint32_t a;
    asm("{ .reg .u64 t; cvta.to.shared.u64 t, %1; cvt.u32.u64 %0, t; }" : "=r"(a) : "l"(p));
    return a;
}
__device__ __forceinline__ uint32_t bf2(float lo, float hi) {   // [15:0]=bf16(lo), [31:16]=bf16(hi)
    uint32_t r;
    asm("cvt.rn.bf16x2.f32 %0, %1, %2;" : "=r"(r) : "f"(hi), "f"(lo));
    return r;
}
__device__ __forceinline__ void cp_async16(uint32_t dst, const float* src) {
    asm volatile("cp.async.cg.shared.global [%0], [%1], 16;" :: "r"(dst), "l"(src));
}
__device__ __forceinline__ void cp_commit() { asm volatile("cp.async.commit_group;"); }
__device__ __forceinline__ void cp_wait0()  { asm volatile("cp.async.wait_group 0;" ::: "memory"); }

__device__ __forceinline__ void ldm4(uint32_t* r, uint32_t a) {
    asm volatile("ldmatrix.sync.aligned.m8n8.x4.shared.b16 {%0,%1,%2,%3}, [%4];"
                 : "=r"(r[0]), "=r"(r[1]), "=r"(r[2]), "=r"(r[3]) : "r"(a));
}
__device__ __forceinline__ void ldm4t(uint32_t* r, uint32_t a) {
    asm volatile("ldmatrix.sync.aligned.m8n8.x4.trans.shared.b16 {%0,%1,%2,%3}, [%4];"
                 : "=r"(r[0]), "=r"(r[1]), "=r"(r[2]), "=r"(r[3]) : "r"(a));
}
__device__ __forceinline__ void ldm2(uint32_t* r, uint32_t a) {
    asm volatile("ldmatrix.sync.aligned.m8n8.x2.shared.b16 {%0,%1}, [%2];"
                 : "=r"(r[0]), "=r"(r[1]) : "r"(a));
}
__device__ __forceinline__ void mma16816(float* d, const uint32_t* a, const uint32_t* b) {
    asm volatile("mma.sync.aligned.m16n8k16.row.col.f32.bf16.bf16.f32 "
                 "{%0,%1,%2,%3}, {%4,%5,%6,%7}, {%8,%9}, {%0,%1,%2,%3};"
                 : "+f"(d[0]), "+f"(d[1]), "+f"(d[2]), "+f"(d[3])
                 : "r"(a[0]), "r"(a[1]), "r"(a[2]), "r"(a[3]), "r"(b[0]), "r"(b[1]));
}

// ---------------------------------------------------------------------------
// Kernel A: cross GEMM (mma) + softmax (frag regs) + aggregation GEMM (mma)
// ---------------------------------------------------------------------------
__global__ void __launch_bounds__(TPB, 1) encnet_main(
    const float* __restrict__ x, const float* __restrict__ cw,
    const float* __restrict__ smth)
{
    extern __shared__ unsigned char smem[];
    const uint32_t sb = smem_u32(smem);
    float*  xs  = (float*)(smem + SM_XS);
    float*  x2s = (float*)(smem + SM_X2);
    float4* c4  = (float4*)(smem + SM_C4);

    const int tid = threadIdx.x, lane = tid & 31, w = tid >> 5;
    const int chunk = blockIdx.x, b = blockIdx.y;
    const float* xg = x + (long)b * CDIM * SEQ + chunk * (SEQ / NCHUNK);

    // prefetch tile 0 into fp32 staging [c][132]
    #pragma unroll
    for (int it = 0; it < 16; it++) {
        int idx = tid + it * TPB;                 // 0..4095 16B chunks
        int cc = idx >> 5, seg = idx & 31;
        cp_async16(sb + SM_XS + (uint32_t)(cc * XS_ST * 4 + seg * 16),
                   xg + (long)cc * SEQ + seg * 4);
    }
    cp_commit();

    // codewords -> bf16 rows CW[k][c]
    for (int i = tid; i < KDIM * CDIM; i += TPB) {
        int r = i >> 7, c = i & 127;
        *(__nv_bfloat16*)(smem + SM_CW + r * (XT_ST * 2) + c * 2) =
            __float2bfloat16(__ldg(cw + i));
    }
    // per-k logit consts: (sk, sk*||cw||^2, -2*sk, 0)
    if (tid < KDIM) {
        const float4* row = (const float4*)(cw + tid * CDIM);
        float c2 = 0.f;
        #pragma unroll
        for (int j = 0; j < CDIM / 4; j++) {
            float4 v = __ldg(row + j);
            c2 += v.x * v.x + v.y * v.y + v.z * v.z + v.w * v.w;
        }
        float s = __ldg(smth + tid);
        c4[tid] = make_float4(s, s * c2, -2.f * s, 0.f);
    }

    // ldmatrix base addresses (constant per thread)
    const int m0 = 16 * w;
    // GEMM1 A (trans, from XT): rows c, cols m
    const uint32_t a1base = sb + SM_XTH +
        (uint32_t)((((lane >> 4) << 3) + (lane & 7)) * 272 + (m0 + (lane & 8)) * 2);
    // GEMM2 A (non-trans, from XT): rows m, cols s
    const uint32_t a2base = sb + SM_XTH +
        (uint32_t)((m0 + (lane & 15)) * 272 + (lane >> 4) * 16);
    // B operands (x2 non-trans): rows n, col-halves
    const uint32_t bof = (uint32_t)((lane & 7) * 272 + (((lane & 15) >> 3)) * 16);
    const uint32_t bcw = sb + SM_CW + bof;
    const uint32_t bat = sb + SM_AT + bof;
    const uint32_t XTLOFF = (uint32_t)(SM_XTL - SM_XTH);

    float acc2[8][4];
    #pragma unroll
    for (int i = 0; i < 8; i++)
        { acc2[i][0] = acc2[i][1] = acc2[i][2] = acc2[i][3] = 0.f; }
    float aAcc = 0.f;

    const int crow = tid >> 1, chalf = tid & 1;

    for (int t = 0; t < NTILE; t++) {
        cp_wait0();
        __syncthreads();   // staging ready; prev GEMM2 done reading XT/AT

        // ---- convert: thread = (c row, half); h-interleaved 4-elem blocks ----
        {
            const float* srow = xs + crow * XS_ST;
            unsigned char* dH = smem + SM_XTH + crow * 272;
            unsigned char* dL = smem + SM_XTL + crow * 272;
            #pragma unroll
            for (int j = 0; j < 16; j++) {
                int s0 = 8 * j + 4 * chalf;
                float4 v = *(const float4*)(srow + s0);
                uint32_t h0 = bf2(v.x, v.y), h1 = bf2(v.z, v.w);
                float rx = v.x - __uint_as_float(h0 << 16);
                float ry = v.y - __uint_as_float(h0 & 0xffff0000u);
                float rz = v.z - __uint_as_float(h1 << 16);
                float rw = v.w - __uint_as_float(h1 & 0xffff0000u);
                uint32_t l0 = bf2(rx, ry), l1 = bf2(rz, rw);
                *(uint2*)(dH + s0 * 2) = make_uint2(h0, h1);
                *(uint2*)(dL + s0 * 2) = make_uint2(l0, l1);
            }
        }
        // ---- x2[s] from staging (conflict-free column reads) ----
        if (tid < STILE) {
            float a = 0.f;
            #pragma unroll 8
            for (int c2 = 0; c2 < CDIM; c2++) {
                float f = xs[c2 * XS_ST + tid];
                a = fmaf(f, f, a);
            }
            x2s[tid] = a;
        }
        __syncthreads();

        // staging free: prefetch next tile (overlaps GEMM1 + softmax + GEMM2)
        if (t + 1 < NTILE) {
            const float* xt1 = xg + (t + 1) * STILE;
            #pragma unroll
            for (int it = 0; it < 16; it++) {
                int idx = tid + it * TPB;
                int cc = idx >> 5, seg = idx & 31;
                cp_async16(sb + SM_XS + (uint32_t)(cc * XS_ST * 4 + seg * 16),
                           xt1 + (long)cc * SEQ + seg * 4);
            }
            cp_commit();
        }

        // ---- GEMM1: cross[s=128, k=64] = (Xh+Xl) . CW^T ----
        float acc1[8][4];
        #pragma unroll
        for (int i = 0; i < 8; i++)
            { acc1[i][0] = acc1[i][1] = acc1[i][2] = acc1[i][3] = 0.f; }
        {
            uint32_t aH[4], aL[4], bb[2];
            #pragma unroll
            for (int kc = 0; kc < 8; kc++) {
                ldm4t(aH, a1base + kc * 4352);            // 16 c-rows * 272B
                ldm4t(aL, a1base + XTLOFF + kc * 4352);
                #pragma unroll
                for (int nt = 0; nt < 8; nt++) {
                    ldm2(bb, bcw + nt * 2176 + kc * 32);  // 8 n-rows*272B ; 16 c-elems*2B
                    mma16816(acc1[nt], aH, bb);
                    mma16816(acc1[nt], aL, bb);
                }
            }
        }

        // ---- softmax on fragments (rows shared by lane quads) ----
        {
            const int g = lane >> 2, q = lane & 3;
            const int s0r = m0 + g;
            float xa = x2s[s0r], xb = x2s[s0r + 8];
            float p0[16], p1[16];
            float mA = -3.4e38f, mB = -3.4e38f;
            #pragma unroll
            for (int nt = 0; nt < 8; nt++) {
                float4 cA = c4[8 * nt + 2 * q];
                float4 cB = c4[8 * nt + 2 * q + 1];
                p0[2*nt]   = fmaf(cA.z, acc1[nt][0], fmaf(cA.x, xa, cA.y));
                p0[2*nt+1] = fmaf(cB.z, acc1[nt][1], fmaf(cB.x, xa, cB.y));
                p1[2*nt]   = fmaf(cA.z, acc1[nt][2], fmaf(cA.x, xb, cA.y));
                p1[2*nt+1] = fmaf(cB.z, acc1[nt][3], fmaf(cB.x, xb, cB.y));
                mA = fmaxf(mA, fmaxf(p0[2*nt], p0[2*nt+1]));
                mB = fmaxf(mB, fmaxf(p1[2*nt], p1[2*nt+1]));
            }
            mA = fmaxf(mA, __shfl_xor_sync(0xffffffffu, mA, 1));
            mA = fmaxf(mA, __shfl_xor_sync(0xffffffffu, mA, 2));
            mB = fmaxf(mB, __shfl_xor_sync(0xffffffffu, mB, 1));
            mB = fmaxf(mB, __shfl_xor_sync(0xffffffffu, mB, 2));
            float sA = 0.f, sB = 0.f;
            #pragma unroll
            for (int j = 0; j < 16; j++) {
                p0[j] = __expf(p0[j] - mA); sA += p0[j];
                p1[j] = __expf(p1[j] - mB); sB += p1[j];
            }
            sA += __shfl_xor_sync(0xffffffffu, sA, 1);
            sA += __shfl_xor_sync(0xffffffffu, sA, 2);
            sB += __shfl_xor_sync(0xffffffffu, sB, 1);
            sB += __shfl_xor_sync(0xffffffffu, sB, 2);
            float iA = 1.f / sA, iB = 1.f / sB;
            #pragma unroll
            for (int nt = 0; nt < 8; nt++) {
                int k0 = 8 * nt + 2 * q;
                unsigned char* base0 = smem + SM_AT + k0 * 272;
                unsigned char* base1 = base0 + 272;
                *(__nv_bfloat16*)(base0 + s0r * 2)       = __float2bfloat16(p0[2*nt]   * iA);
                *(__nv_bfloat16*)(base1 + s0r * 2)       = __float2bfloat16(p0[2*nt+1] * iA);
                *(__nv_bfloat16*)(base0 + (s0r + 8) * 2) = __float2bfloat16(p1[2*nt]   * iB);
                *(__nv_bfloat16*)(base1 + (s0r + 8) * 2) = __float2bfloat16(p1[2*nt+1] * iB);
            }
        }
        __syncthreads();   // AT complete for all warps

        // ---- per-k sum of bf16 a (consistent with GEMM2 operand) ----
        if (tid < KDIM) {
            float acc = 0.f;
            const __nv_bfloat162* row = (const __nv_bfloat162*)(smem + SM_AT + tid * 272);
            #pragma unroll 8
            for (int j = 0; j < 64; j++) {
                float2 f = __bfloat1622float2(row[j]);
                acc += f.x + f.y;
            }
            aAcc += acc;
        }

        // ---- GEMM2: e[c=128, k=64] += (Xh+Xl) . a ----
        {
            uint32_t aH[4], aL[4], bb[2];
            #pragma unroll
            for (int kc = 0; kc < 8; kc++) {
                ldm4(aH, a2base + kc * 32);               // 16 s-elems * 2B
                ldm4(aL, a2base + XTLOFF + kc * 32);
                #pragma unroll
                for (int nt = 0; nt < 8; nt++) {
                    ldm2(bb, bat + nt * 2176 + kc * 32);
                    mma16816(acc2[nt], aH, bb);
                    mma16816(acc2[nt], aL, bb);
                }
            }
        }
    }

    // ---- epilogue: write chunk partials ----
    {
        float* ep = g_epart + ((long)(chunk * BDIM + b) * KDIM) * CDIM;
        const int c0r = m0 + (lane >> 2), q = lane & 3;
        #pragma unroll
        for (int nt = 0; nt < 8; nt++) {
            int k0 = 8 * nt + 2 * q;
            ep[k0 * CDIM + c0r]           = acc2[nt][0];
            ep[(k0 + 1) * CDIM + c0r]     = acc2[nt][1];
            ep[k0 * CDIM + c0r + 8]       = acc2[nt][2];
            ep[(k0 + 1) * CDIM + c0r + 8] = acc2[nt][3];
        }
        if (tid < KDIM) g_Apart[(chunk * BDIM + b) * KDIM + tid] = aAcc;
    }
}

// ---------------------------------------------------------------------------
// Kernel B: reduce chunk partials, subtract A*cw, BN batch stats per k
// ---------------------------------------------------------------------------
__global__ void encnet_stats(const float* __restrict__ cw,
                             const float* __restrict__ bnw,
                             const float* __restrict__ bnb)
{
    const int k = blockIdx.x, tid = threadIdx.x;   // 256 threads
    __shared__ float Ab[BDIM];
    __shared__ float red[256];

    if (tid < BDIM) {
        float a = 0.f;
        #pragma unroll
        for (int ch = 0; ch < NCHUNK; ch++) a += g_Apart[(ch * BDIM + tid) * KDIM + k];
        Ab[tid] = a;
    }
    __syncthreads();

    float sum = 0.f, ss = 0.f;
    for (int i = tid; i < BDIM * CDIM; i += 256) {
        int bb = i >> 7, c = i & 127;
        float v = 0.f;
        #pragma unroll
        for (int ch = 0; ch < NCHUNK; ch++)
            v += g_epart[(((long)ch * BDIM + bb) * KDIM + k) * CDIM + c];
        v -= Ab[bb] * __ldg(cw + k * CDIM + c);
        g_ecorr[(bb * KDIM + k) * CDIM + c] = v;
        sum += v;
        ss = fmaf(v, v, ss);
    }
    red[tid] = sum; __syncthreads();
    for (int o = 128; o > 0; o >>= 1) { if (tid < o) red[tid] += red[tid + o]; __syncthreads(); }
    float tsum = red[0]; __syncthreads();
    red[tid] = ss; __syncthreads();
    for (int o = 128; o > 0; o >>= 1) { if (tid < o) red[tid] += red[tid + o]; __syncthreads(); }
    if (tid == 0) {
        const float n = (float)(BDIM * CDIM);
        float mean = tsum / n;
        float var = red[0] / n - mean * mean;
        float rstd = rsqrtf(var + 1e-5f);
        float g = rstd * __ldg(bnw + k);
        g_gk[k] = g;
        g_hk[k] = __ldg(bnb + k) - mean * g;
    }
}

// ---------------------------------------------------------------------------
// Kernel C: e_norm (mean of relu over k) + FC + sigmoid -> per-(b,c) scale
// ---------------------------------------------------------------------------
__global__ void encnet_fc(const float* __restrict__ fcw, const float* __restrict__ fcb)
{
    const int b = blockIdx.x, tid = threadIdx.x;   // 128 threads
    __shared__ float en[CDIM];
    float acc = 0.f;
    #pragma unroll 4
    for (int k = 0; k < KDIM; k++) {
        float v = g_ecorr[(b * KDIM + k) * CDIM + tid];
        acc += fmaxf(fmaf(v, g_gk[k], g_hk[k]), 0.f);
    }
    en[tid] = acc * (1.f / (float)KDIM);
    __syncthreads();

    float lg = __ldg(fcb + tid);
    const float* wr = fcw + tid * CDIM;
    #pragma unroll 4
    for (int c2 = 0; c2 < CDIM; c2++) lg = fmaf(en[c2], __ldg(wr + c2), lg);
    g_scale[b * CDIM + tid] = 1.f / (1.f + __expf(-lg));
}

// ---------------------------------------------------------------------------
// Kernel D: out = x * scale  (memory bound)
// ---------------------------------------------------------------------------
__global__ void encnet_scale(const float4* __restrict__ x4, float4* __restrict__ out4)
{
    const int total = (BDIM * CDIM * SEQ) / 4;
    for (int i = blockIdx.x * blockDim.x + threadIdx.x; i < total;
         i += gridDim.x * blockDim.x) {
        float s = __ldg(&g_scale[i >> 12]);
        float4 v = __ldg(x4 + i);
        v.x *= s; v.y *= s; v.z *= s; v.w *= s;
        out4[i] = v;
    }
}

// ---------------------------------------------------------------------------
extern "C" void kernel_launch(void* const* d_in, const int* in_sizes, int n_in,
                              void* d_out, int out_size)
{
    const float* x    = (const float*)d_in[0];
    const float* cw   = (const float*)d_in[1];
    const float* smth = (const float*)d_in[2];
    const float* bnw  = (const float*)d_in[3];
    const float* bnb  = (const float*)d_in[4];
    const float* fcw  = (const float*)d_in[5];
    const float* fcb  = (const float*)d_in[6];
    float* out = (float*)d_out;

    cudaFuncSetAttribute(encnet_main, cudaFuncAttributeMaxDynamicSharedMemorySize, SMEM_BYTES);

    encnet_main <<<dim3(NCHUNK, BDIM), TPB, SMEM_BYTES>>>(x, cw, smth);
    encnet_stats<<<KDIM, 256>>>(cw, bnw, bnb);
    encnet_fc   <<<BDIM, CDIM>>>(fcw, fcb);
    encnet_scale<<<4096, 256>>>((const float4*)x, (float4*)out);
}

// round 9
// speedup vs baseline: 3.0205x; 1.1056x over previous
#include <cuda_runtime.h>
#include <cuda_bf16.h>
#include <cstdint>

#define SEQ    16384
#define CDIM   128
#define KDIM   64
#define BDIM   16
#define NCHUNK 16
#define STILE  128
#define TPB    256
#define NTILE  ((SEQ / NCHUNK) / STILE)   // 8

#define XT_ST  136       // bf16/row -> 272B (ldmatrix conflict-free)
#define AT_ST  72        // bf16/row -> 144B

// smem byte offsets
#define SM_X2   0                              // x2[128] f32
#define SM_X2P  512                            // x2 partials [8][128] f32 (4096)
#define SM_ATP  4608                           // aAcc partials [8][64] f32 (2048)
#define SM_C4   6656                           // float4[64] per-k consts (1024)
#define SM_XTH  7680                           // X^T[c][s] hi bf16 128x136 (34816)
#define SM_XTL  42496                          // lo (34816)
#define SM_CW   77312                          // CW[k][c] bf16 64x136 (17408)
#define SM_AT   94720                          // a[s][k] bf16 128x72 (18432)
#define SMEM_BYTES 113152                      // -> 2 CTAs/SM

// deterministic scratch
__device__ float g_epart[(long)NCHUNK * BDIM * KDIM * CDIM];
__device__ float g_Apart[NCHUNK * BDIM * KDIM];
__device__ float g_ecorr[BDIM * KDIM * CDIM];
__device__ float g_gk[KDIM];
__device__ float g_hk[KDIM];
__device__ float g_scale[BDIM * CDIM];

__device__ __forceinline__ uint32_t smem_u32(const void* p) {
    uint32_t a;
    asm("{ .reg .u64 t; cvta.to.shared.u64 t, %1; cvt.u32.u64 %0, t; }" : "=r"(a) : "l"(p));
    return a;
}
__device__ __forceinline__ uint32_t bf2(float lo, float hi) {   // [15:0]=bf16(lo), [31:16]=bf16(hi)
    uint32_t r;
    asm("cvt.rn.bf16x2.f32 %0, %1, %2;" : "=r"(r) : "f"(hi), "f"(lo));
    return r;
}
__device__ __forceinline__ void ldm4(uint32_t* r, uint32_t a) {
    asm volatile("ldmatrix.sync.aligned.m8n8.x4.shared.b16 {%0,%1,%2,%3}, [%4];"
                 : "=r"(r[0]), "=r"(r[1]), "=r"(r[2]), "=r"(r[3]) : "r"(a));
}
__device__ __forceinline__ void ldm4t(uint32_t* r, uint32_t a) {
    asm volatile("ldmatrix.sync.aligned.m8n8.x4.trans.shared.b16 {%0,%1,%2,%3}, [%4];"
                 : "=r"(r[0]), "=r"(r[1]), "=r"(r[2]), "=r"(r[3]) : "r"(a));
}
__device__ __forceinline__ void ldm2(uint32_t* r, uint32_t a) {
    asm volatile("ldmatrix.sync.aligned.m8n8.x2.shared.b16 {%0,%1}, [%2];"
                 : "=r"(r[0]), "=r"(r[1]) : "r"(a));
}
__device__ __forceinline__ void ldm2t(uint32_t* r, uint32_t a) {
    asm volatile("ldmatrix.sync.aligned.m8n8.x2.trans.shared.b16 {%0,%1}, [%2];"
                 : "=r"(r[0]), "=r"(r[1]) : "r"(a));
}
__device__ __forceinline__ void mma16816(float* d, const uint32_t* a, const uint32_t* b) {
    asm volatile("mma.sync.aligned.m16n8k16.row.col.f32.bf16.bf16.f32 "
                 "{%0,%1,%2,%3}, {%4,%5,%6,%7}, {%8,%9}, {%0,%1,%2,%3};"
                 : "+f"(d[0]), "+f"(d[1]), "+f"(d[2]), "+f"(d[3])
                 : "r"(a[0]), "r"(a[1]), "r"(a[2]), "r"(a[3]), "r"(b[0]), "r"(b[1]));
}

// ---------------------------------------------------------------------------
// Kernel A: cross GEMM (mma) + softmax (frag regs) + aggregation GEMM (mma)
// 2 CTAs/SM: phases of co-resident CTAs interleave.
// ---------------------------------------------------------------------------
__global__ void __launch_bounds__(TPB, 2) encnet_main(
    const float* __restrict__ x, const float* __restrict__ cw,
    const float* __restrict__ smth)
{
    extern __shared__ unsigned char smem[];
    const uint32_t sb = smem_u32(smem);
    float*  x2s = (float*)(smem + SM_X2);
    float*  x2p = (float*)(smem + SM_X2P);
    float*  atp = (float*)(smem + SM_ATP);
    float4* c4  = (float4*)(smem + SM_C4);

    const int tid = threadIdx.x, lane = tid & 31, w = tid >> 5;
    const int chunk = blockIdx.x, b = blockIdx.y;
    const float* xg = x + (long)b * CDIM * SEQ + chunk * (SEQ / NCHUNK);

    // codewords -> bf16 rows CW[k][c]
    for (int i = tid; i < KDIM * CDIM; i += TPB) {
        int r = i >> 7, c = i & 127;
        *(__nv_bfloat16*)(smem + SM_CW + r * 272 + c * 2) =
            __float2bfloat16(__ldg(cw + i));
    }
    // per-k logit consts: (sk, sk*||cw||^2, -2*sk, 0)
    if (tid < KDIM) {
        const float4* row = (const float4*)(cw + tid * CDIM);
        float c2 = 0.f;
        #pragma unroll
        for (int j = 0; j < CDIM / 4; j++) {
            float4 v = __ldg(row + j);
            c2 += v.x * v.x + v.y * v.y + v.z * v.z + v.w * v.w;
        }
        float s = __ldg(smth + tid);
        c4[tid] = make_float4(s, s * c2, -2.f * s, 0.f);
    }

    // ldmatrix base addresses (constant per thread)
    const int m0 = 16 * w;
    // GEMM1 A (trans, from XT): rows c, cols m
    const uint32_t a1base = sb + SM_XTH +
        (uint32_t)((((lane >> 4) << 3) + (lane & 7)) * 272 + (m0 + (lane & 8)) * 2);
    // GEMM2 A (non-trans, from XTH): rows m(c), cols s
    const uint32_t a2base = sb + SM_XTH +
        (uint32_t)((m0 + (lane & 15)) * 272 + (lane >> 4) * 16);
    // GEMM1 B (CW non-trans): rows k, col-halves along c
    const uint32_t bcw = sb + SM_CW +
        (uint32_t)((lane & 7) * 272 + (((lane & 15) >> 3)) * 16);
    // GEMM2 B (a trans, [s][k]): rows s, cols k
    const uint32_t bat = sb + SM_AT + (uint32_t)((lane & 15) * 144);
    const uint32_t XTLOFF = (uint32_t)(SM_XTL - SM_XTH);

    float acc2[8][4];
    #pragma unroll
    for (int i = 0; i < 8; i++)
        { acc2[i][0] = acc2[i][1] = acc2[i][2] = acc2[i][3] = 0.f; }
    float aAcc = 0.f;

    __syncthreads();   // CW/c4 ready

    for (int t = 0; t < NTILE; t++) {
        // ---- convert: direct LDG -> hi/lo bf16 XT; x2 partials in regs ----
        {
            float4 x2a = make_float4(0.f, 0.f, 0.f, 0.f);
            const float* xt0 = xg + t * STILE;
            #pragma unroll
            for (int it = 0; it < 16; it++) {
                int cc = w + it * 8;                       // warp = full row
                float4 v = __ldg((const float4*)(xt0 + (long)cc * SEQ) + lane);
                x2a.x = fmaf(v.x, v.x, x2a.x);
                x2a.y = fmaf(v.y, v.y, x2a.y);
                x2a.z = fmaf(v.z, v.z, x2a.z);
                x2a.w = fmaf(v.w, v.w, x2a.w);
                uint32_t h0 = bf2(v.x, v.y), h1 = bf2(v.z, v.w);
                float rx = v.x - __uint_as_float(h0 << 16);
                float ry = v.y - __uint_as_float(h0 & 0xffff0000u);
                float rz = v.z - __uint_as_float(h1 << 16);
                float rw = v.w - __uint_as_float(h1 & 0xffff0000u);
                uint32_t l0 = bf2(rx, ry), l1 = bf2(rz, rw);
                *(uint2*)(smem + SM_XTH + cc * 272 + lane * 8) = make_uint2(h0, h1);
                *(uint2*)(smem + SM_XTL + cc * 272 + lane * 8) = make_uint2(l0, l1);
            }
            *(float4*)(x2p + w * 128 + lane * 4) = x2a;
        }
        __syncthreads();
        if (tid < STILE) {
            float a = 0.f;
            #pragma unroll
            for (int ww = 0; ww < 8; ww++) a += x2p[ww * 128 + tid];
            x2s[tid] = a;
        }
        __syncthreads();

        // ---- GEMM1: cross[s=128, k=64] = (Xh+Xl) . CW^T ----
        float acc1[8][4];
        #pragma unroll
        for (int i = 0; i < 8; i++)
            { acc1[i][0] = acc1[i][1] = acc1[i][2] = acc1[i][3] = 0.f; }
        {
            uint32_t aH[4], aL[4], bb[2];
            #pragma unroll
            for (int kc = 0; kc < 8; kc++) {
                ldm4t(aH, a1base + kc * 4352);            // 16 c-rows * 272B
                ldm4t(aL, a1base + XTLOFF + kc * 4352);
                #pragma unroll
                for (int nt = 0; nt < 8; nt++) {
                    ldm2(bb, bcw + nt * 2176 + kc * 32);
                    mma16816(acc1[nt], aH, bb);
                    mma16816(acc1[nt], aL, bb);
                }
            }
        }

        // ---- softmax on fragments; store a[s][k] bf16; warp-reduce sum_s a ----
        {
            const int g = lane >> 2, q = lane & 3;
            const int s0r = m0 + g;
            float xa = x2s[s0r], xb = x2s[s0r + 8];
            float p0[16], p1[16];
            float mA = -3.4e38f, mB = -3.4e38f;
            #pragma unroll
            for (int nt = 0; nt < 8; nt++) {
                float4 cA = c4[8 * nt + 2 * q];
                float4 cB = c4[8 * nt + 2 * q + 1];
                p0[2*nt]   = fmaf(cA.z, acc1[nt][0], fmaf(cA.x, xa, cA.y));
                p0[2*nt+1] = fmaf(cB.z, acc1[nt][1], fmaf(cB.x, xa, cB.y));
                p1[2*nt]   = fmaf(cA.z, acc1[nt][2], fmaf(cA.x, xb, cA.y));
                p1[2*nt+1] = fmaf(cB.z, acc1[nt][3], fmaf(cB.x, xb, cB.y));
                mA = fmaxf(mA, fmaxf(p0[2*nt], p0[2*nt+1]));
                mB = fmaxf(mB, fmaxf(p1[2*nt], p1[2*nt+1]));
            }
            mA = fmaxf(mA, __shfl_xor_sync(0xffffffffu, mA, 1));
            mA = fmaxf(mA, __shfl_xor_sync(0xffffffffu, mA, 2));
            mB = fmaxf(mB, __shfl_xor_sync(0xffffffffu, mB, 1));
            mB = fmaxf(mB, __shfl_xor_sync(0xffffffffu, mB, 2));
            float sA = 0.f, sB = 0.f;
            #pragma unroll
            for (int j = 0; j < 16; j++) {
                p0[j] = __expf(p0[j] - mA); sA += p0[j];
                p1[j] = __expf(p1[j] - mB); sB += p1[j];
            }
            sA += __shfl_xor_sync(0xffffffffu, sA, 1);
            sA += __shfl_xor_sync(0xffffffffu, sA, 2);
            sB += __shfl_xor_sync(0xffffffffu, sB, 1);
            sB += __shfl_xor_sync(0xffffffffu, sB, 2);
            float iA = 1.f / sA, iB = 1.f / sB;
            #pragma unroll
            for (int nt = 0; nt < 8; nt++) {
                const int k0 = 8 * nt + 2 * q;
                float a00 = p0[2*nt] * iA, a01 = p0[2*nt+1] * iA;
                float a10 = p1[2*nt] * iB, a11 = p1[2*nt+1] * iB;
                *(uint32_t*)(smem + SM_AT + s0r * 144 + k0 * 2)       = bf2(a00, a01);
                *(uint32_t*)(smem + SM_AT + (s0r + 8) * 144 + k0 * 2) = bf2(a10, a11);
                // per-k partial sums over this warp's 16 s rows
                float v0 = a00 + a10, v1 = a01 + a11;
                v0 += __shfl_xor_sync(0xffffffffu, v0, 4);
                v1 += __shfl_xor_sync(0xffffffffu, v1, 4);
                v0 += __shfl_xor_sync(0xffffffffu, v0, 8);
                v1 += __shfl_xor_sync(0xffffffffu, v1, 8);
                v0 += __shfl_xor_sync(0xffffffffu, v0, 16);
                v1 += __shfl_xor_sync(0xffffffffu, v1, 16);
                if (g == 0) {
                    atp[w * 64 + k0]     = v0;
                    atp[w * 64 + k0 + 1] = v1;
                }
            }
        }
        __syncthreads();   // AT + atp ready

        if (tid < KDIM) {
            float a = 0.f;
            #pragma unroll
            for (int ww = 0; ww < 8; ww++) a += atp[ww * 64 + tid];
            aAcc += a;
        }

        // ---- GEMM2: e[c=128, k=64] += Xh . a ----
        {
            uint32_t aH[4], bb[2];
            #pragma unroll
            for (int kc = 0; kc < 8; kc++) {
                ldm4(aH, a2base + kc * 32);               // 16 s-elems * 2B
                #pragma unroll
                for (int nt = 0; nt < 8; nt++) {
                    ldm2t(bb, bat + kc * 2304 + nt * 16); // 16 s-rows*144B ; 8 k*2B
                    mma16816(acc2[nt], aH, bb);
                }
            }
        }
        __syncthreads();   // GEMM2 reads done before next tile's XT/AT rewrite
    }

    // ---- epilogue: write chunk partials ----
    {
        float* ep = g_epart + ((long)(chunk * BDIM + b) * KDIM) * CDIM;
        const int c0r = m0 + (lane >> 2), q = lane & 3;
        #pragma unroll
        for (int nt = 0; nt < 8; nt++) {
            int k0 = 8 * nt + 2 * q;
            ep[k0 * CDIM + c0r]           = acc2[nt][0];
            ep[(k0 + 1) * CDIM + c0r]     = acc2[nt][1];
            ep[k0 * CDIM + c0r + 8]       = acc2[nt][2];
            ep[(k0 + 1) * CDIM + c0r + 8] = acc2[nt][3];
        }
        if (tid < KDIM) g_Apart[(chunk * BDIM + b) * KDIM + tid] = aAcc;
    }
}

// ---------------------------------------------------------------------------
// Kernel B: reduce chunk partials, subtract A*cw, BN batch stats per k
// ---------------------------------------------------------------------------
__global__ void encnet_stats(const float* __restrict__ cw,
                             const float* __restrict__ bnw,
                             const float* __restrict__ bnb)
{
    const int k = blockIdx.x, tid = threadIdx.x;   // 256 threads
    __shared__ float Ab[BDIM];
    __shared__ float red[256];

    if (tid < BDIM) {
        float a = 0.f;
        #pragma unroll
        for (int ch = 0; ch < NCHUNK; ch++) a += g_Apart[(ch * BDIM + tid) * KDIM + k];
        Ab[tid] = a;
    }
    __syncthreads();

    float sum = 0.f, ss = 0.f;
    for (int i = tid; i < BDIM * CDIM; i += 256) {
        int bb = i >> 7, c = i & 127;
        float v = 0.f;
        #pragma unroll
        for (int ch = 0; ch < NCHUNK; ch++)
            v += g_epart[(((long)ch * BDIM + bb) * KDIM + k) * CDIM + c];
        v -= Ab[bb] * __ldg(cw + k * CDIM + c);
        g_ecorr[(bb * KDIM + k) * CDIM + c] = v;
        sum += v;
        ss = fmaf(v, v, ss);
    }
    red[tid] = sum; __syncthreads();
    for (int o = 128; o > 0; o >>= 1) { if (tid < o) red[tid] += red[tid + o]; __syncthreads(); }
    float tsum = red[0]; __syncthreads();
    red[tid] = ss; __syncthreads();
    for (int o = 128; o > 0; o >>= 1) { if (tid < o) red[tid] += red[tid + o]; __syncthreads(); }
    if (tid == 0) {
        const float n = (float)(BDIM * CDIM);
        float mean = tsum / n;
        float var = red[0] / n - mean * mean;
        float rstd = rsqrtf(var + 1e-5f);
        float g = rstd * __ldg(bnw + k);
        g_gk[k] = g;
        g_hk[k] = __ldg(bnb + k) - mean * g;
    }
}

// ---------------------------------------------------------------------------
// Kernel C: e_norm (mean of relu over k) + FC + sigmoid -> per-(b,c) scale
// ---------------------------------------------------------------------------
__global__ void encnet_fc(const float* __restrict__ fcw, const float* __restrict__ fcb)
{
    const int b = blockIdx.x, tid = threadIdx.x;   // 128 threads
    __shared__ float en[CDIM];
    float acc = 0.f;
    #pragma unroll 4
    for (int k = 0; k < KDIM; k++) {
        float v = g_ecorr[(b * KDIM + k) * CDIM + tid];
        acc += fmaxf(fmaf(v, g_gk[k], g_hk[k]), 0.f);
    }
    en[tid] = acc * (1.f / (float)KDIM);
    __syncthreads();

    float lg = __ldg(fcb + tid);
    const float* wr = fcw + tid * CDIM;
    #pragma unroll 4
    for (int c2 = 0; c2 < CDIM; c2++) lg = fmaf(en[c2], __ldg(wr + c2), lg);
    g_scale[b * CDIM + tid] = 1.f / (1.f + __expf(-lg));
}

// ---------------------------------------------------------------------------
// Kernel D: out = x * scale  (memory bound)
// ---------------------------------------------------------------------------
__global__ void encnet_scale(const float4* __restrict__ x4, float4* __restrict__ out4)
{
    const int total = (BDIM * CDIM * SEQ) / 4;
    for (int i = blockIdx.x * blockDim.x + threadIdx.x; i < total;
         i += gridDim.x * blockDim.x) {
        float s = __ldg(&g_scale[i >> 12]);
        float4 v = __ldg(x4 + i);
        v.x *= s; v.y *= s; v.z *= s; v.w *= s;
        out4[i] = v;
    }
}

// ---------------------------------------------------------------------------
extern "C" void kernel_launch(void* const* d_in, const int* in_sizes, int n_in,
                              void* d_out, int out_size)
{
    const float* x    = (const float*)d_in[0];
    const float* cw   = (const float*)d_in[1];
    const float* smth = (const float*)d_in[2];
    const float* bnw  = (const float*)d_in[3];
    const float* bnb  = (const float*)d_in[4];
    const float* fcw  = (const float*)d_in[5];
    const float* fcb  = (const float*)d_in[6];
    float* out = (float*)d_out;

    cudaFuncSetAttribute(encnet_main, cudaFuncAttributeMaxDynamicSharedMemorySize, SMEM_BYTES);

    encnet_main <<<dim3(NCHUNK, BDIM), TPB, SMEM_BYTES>>>(x, cw, smth);
    encnet_stats<<<KDIM, 256>>>(cw, bnw, bnb);
    encnet_fc   <<<BDIM, CDIM>>>(fcw, fcb);
    encnet_scale<<<4096, 256>>>((const float4*)x, (float4*)out);
}

// round 10
// speedup vs baseline: 3.3380x; 1.1051x over previous
#include <cuda_runtime.h>
#include <cuda_bf16.h>
#include <cstdint>

#define SEQ    16384
#define CDIM   128
#define KDIM   64
#define BDIM   16
#define NCHUNK 16
#define STILE  128
#define TPB    256
#define NTILE  ((SEQ / NCHUNK) / STILE)   // 8

// smem byte offsets
#define SM_X2   0                              // x2[128] f32 (512)
#define SM_X2P  512                            // x2 partials [8][128] f32 (4096)
#define SM_ATP  4608                           // aAcc partials [8][64] f32 (2048)
#define SM_C4   6656                           // float4[64] per-k consts (1024)
#define SM_XTH  7680                           // X^T[c][s] bf16 128x136 (34816)
#define SM_CW   42496                          // CW[k][c] bf16 64x136 (17408)
#define SM_AT   59904                          // a[s][k] bf16 128x72 (18432)
#define SMEM_BYTES 78336                       // -> 2 CTAs/SM (156.7 KB)

// deterministic scratch
__device__ float g_epart[(long)NCHUNK * BDIM * KDIM * CDIM];
__device__ float g_Apart[NCHUNK * BDIM * KDIM];
__device__ float g_ecorr[BDIM * KDIM * CDIM];
__device__ float g_gk[KDIM];
__device__ float g_hk[KDIM];
__device__ float g_scale[BDIM * CDIM];

__device__ __forceinline__ uint32_t smem_u32(const void* p) {
    uint32_t a;
    asm("{ .reg .u64 t; cvta.to.shared.u64 t, %1; cvt.u32.u64 %0, t; }" : "=r"(a) : "l"(p));
    return a;
}
__device__ __forceinline__ uint32_t bf2(float lo, float hi) {   // [15:0]=bf16(lo), [31:16]=bf16(hi)
    uint32_t r;
    asm("cvt.rn.bf16x2.f32 %0, %1, %2;" : "=r"(r) : "f"(hi), "f"(lo));
    return r;
}
__device__ __forceinline__ void ldm4(uint32_t* r, uint32_t a) {
    asm volatile("ldmatrix.sync.aligned.m8n8.x4.shared.b16 {%0,%1,%2,%3}, [%4];"
                 : "=r"(r[0]), "=r"(r[1]), "=r"(r[2]), "=r"(r[3]) : "r"(a));
}
__device__ __forceinline__ void ldm4t(uint32_t* r, uint32_t a) {
    asm volatile("ldmatrix.sync.aligned.m8n8.x4.trans.shared.b16 {%0,%1,%2,%3}, [%4];"
                 : "=r"(r[0]), "=r"(r[1]), "=r"(r[2]), "=r"(r[3]) : "r"(a));
}
__device__ __forceinline__ void ldm2(uint32_t* r, uint32_t a) {
    asm volatile("ldmatrix.sync.aligned.m8n8.x2.shared.b16 {%0,%1}, [%2];"
                 : "=r"(r[0]), "=r"(r[1]) : "r"(a));
}
__device__ __forceinline__ void ldm2t(uint32_t* r, uint32_t a) {
    asm volatile("ldmatrix.sync.aligned.m8n8.x2.trans.shared.b16 {%0,%1}, [%2];"
                 : "=r"(r[0]), "=r"(r[1]) : "r"(a));
}
__device__ __forceinline__ void mma16816(float* d, const uint32_t* a, const uint32_t* b) {
    asm volatile("mma.sync.aligned.m16n8k16.row.col.f32.bf16.bf16.f32 "
                 "{%0,%1,%2,%3}, {%4,%5,%6,%7}, {%8,%9}, {%0,%1,%2,%3};"
                 : "+f"(d[0]), "+f"(d[1]), "+f"(d[2]), "+f"(d[3])
                 : "r"(a[0]), "r"(a[1]), "r"(a[2]), "r"(a[3]), "r"(b[0]), "r"(b[1]));
}

// ---------------------------------------------------------------------------
// Kernel A: cross GEMM (mma) + softmax (frag regs) + aggregation GEMM (mma)
// 2 CTAs/SM: phases of co-resident CTAs interleave.
// ---------------------------------------------------------------------------
__global__ void __launch_bounds__(TPB, 2) encnet_main(
    const float* __restrict__ x, const float* __restrict__ cw,
    const float* __restrict__ smth)
{
    extern __shared__ unsigned char smem[];
    const uint32_t sb = smem_u32(smem);
    float*  x2s = (float*)(smem + SM_X2);
    float*  x2p = (float*)(smem + SM_X2P);
    float*  atp = (float*)(smem + SM_ATP);
    float4* c4  = (float4*)(smem + SM_C4);

    const int tid = threadIdx.x, lane = tid & 31, w = tid >> 5;
    const int chunk = blockIdx.x, b = blockIdx.y;
    const float* xg = x + (long)b * CDIM * SEQ + chunk * (SEQ / NCHUNK);

    // codewords -> bf16 rows CW[k][c]
    for (int i = tid; i < KDIM * CDIM; i += TPB) {
        int r = i >> 7, c = i & 127;
        *(__nv_bfloat16*)(smem + SM_CW + r * 272 + c * 2) =
            __float2bfloat16(__ldg(cw + i));
    }
    // per-k logit consts: (sk, sk*||cw||^2, -2*sk, 0)
    if (tid < KDIM) {
        const float4* row = (const float4*)(cw + tid * CDIM);
        float c2 = 0.f;
        #pragma unroll
        for (int j = 0; j < CDIM / 4; j++) {
            float4 v = __ldg(row + j);
            c2 += v.x * v.x + v.y * v.y + v.z * v.z + v.w * v.w;
        }
        float s = __ldg(smth + tid);
        c4[tid] = make_float4(s, s * c2, -2.f * s, 0.f);
    }

    // ldmatrix base addresses (constant per thread)
    const int m0 = 16 * w;
    // GEMM1 A (trans, from XT): rows c, cols m(s)
    const uint32_t a1base = sb + SM_XTH +
        (uint32_t)((((lane >> 4) << 3) + (lane & 7)) * 272 + (m0 + (lane & 8)) * 2);
    // GEMM2 A (non-trans, from XT): rows m(c), cols s
    const uint32_t a2base = sb + SM_XTH +
        (uint32_t)((m0 + (lane & 15)) * 272 + (lane >> 4) * 16);
    // GEMM1 B (CW non-trans): rows k, col-halves along c
    const uint32_t bcw = sb + SM_CW +
        (uint32_t)((lane & 7) * 272 + (((lane & 15) >> 3)) * 16);
    // GEMM2 B (a trans, [s][k]): rows s, cols k
    const uint32_t bat = sb + SM_AT + (uint32_t)((lane & 15) * 144);

    float acc2[8][4];
    #pragma unroll
    for (int i = 0; i < 8; i++)
        { acc2[i][0] = acc2[i][1] = acc2[i][2] = acc2[i][3] = 0.f; }
    float aAcc = 0.f;

    __syncthreads();   // CW/c4 ready

    for (int t = 0; t < NTILE; t++) {
        // ---- convert: direct LDG -> bf16 XT; x2 partials in regs ----
        {
            float4 x2a = make_float4(0.f, 0.f, 0.f, 0.f);
            const float* xt0 = xg + t * STILE;
            #pragma unroll
            for (int it = 0; it < 16; it++) {
                int cc = w + it * 8;                       // warp = full row
                float4 v = __ldg((const float4*)(xt0 + (long)cc * SEQ) + lane);
                x2a.x = fmaf(v.x, v.x, x2a.x);
                x2a.y = fmaf(v.y, v.y, x2a.y);
                x2a.z = fmaf(v.z, v.z, x2a.z);
                x2a.w = fmaf(v.w, v.w, x2a.w);
                uint32_t h0 = bf2(v.x, v.y), h1 = bf2(v.z, v.w);
                *(uint2*)(smem + SM_XTH + cc * 272 + lane * 8) = make_uint2(h0, h1);
            }
            *(float4*)(x2p + w * 128 + lane * 4) = x2a;
        }
        __syncthreads();
        if (tid < STILE) {
            float a = 0.f;
            #pragma unroll
            for (int ww = 0; ww < 8; ww++) a += x2p[ww * 128 + tid];
            x2s[tid] = a;
        }
        __syncthreads();

        // ---- GEMM1: cross[s=128, k=64] = Xh . CW^T ----
        float acc1[8][4];
        #pragma unroll
        for (int i = 0; i < 8; i++)
            { acc1[i][0] = acc1[i][1] = acc1[i][2] = acc1[i][3] = 0.f; }
        {
            uint32_t aH[4], bb[2];
            #pragma unroll
            for (int kc = 0; kc < 8; kc++) {
                ldm4t(aH, a1base + kc * 4352);            // 16 c-rows * 272B
                #pragma unroll
                for (int nt = 0; nt < 8; nt++) {
                    ldm2(bb, bcw + nt * 2176 + kc * 32);
                    mma16816(acc1[nt], aH, bb);
                }
            }
        }

        // ---- softmax on fragments; store a[s][k] bf16; warp-reduce sum_s a ----
        {
            const int g = lane >> 2, q = lane & 3;
            const int s0r = m0 + g;
            float xa = x2s[s0r], xb = x2s[s0r + 8];
            float p0[16], p1[16];
            float mA = -3.4e38f, mB = -3.4e38f;
            #pragma unroll
            for (int nt = 0; nt < 8; nt++) {
                float4 cA = c4[8 * nt + 2 * q];
                float4 cB = c4[8 * nt + 2 * q + 1];
                p0[2*nt]   = fmaf(cA.z, acc1[nt][0], fmaf(cA.x, xa, cA.y));
                p0[2*nt+1] = fmaf(cB.z, acc1[nt][1], fmaf(cB.x, xa, cB.y));
                p1[2*nt]   = fmaf(cA.z, acc1[nt][2], fmaf(cA.x, xb, cA.y));
                p1[2*nt+1] = fmaf(cB.z, acc1[nt][3], fmaf(cB.x, xb, cB.y));
                mA = fmaxf(mA, fmaxf(p0[2*nt], p0[2*nt+1]));
                mB = fmaxf(mB, fmaxf(p1[2*nt], p1[2*nt+1]));
            }
            mA = fmaxf(mA, __shfl_xor_sync(0xffffffffu, mA, 1));
            mA = fmaxf(mA, __shfl_xor_sync(0xffffffffu, mA, 2));
            mB = fmaxf(mB, __shfl_xor_sync(0xffffffffu, mB, 1));
            mB = fmaxf(mB, __shfl_xor_sync(0xffffffffu, mB, 2));
            float sA = 0.f, sB = 0.f;
            #pragma unroll
            for (int j = 0; j < 16; j++) {
                p0[j] = __expf(p0[j] - mA); sA += p0[j];
                p1[j] = __expf(p1[j] - mB); sB += p1[j];
            }
            sA += __shfl_xor_sync(0xffffffffu, sA, 1);
            sA += __shfl_xor_sync(0xffffffffu, sA, 2);
            sB += __shfl_xor_sync(0xffffffffu, sB, 1);
            sB += __shfl_xor_sync(0xffffffffu, sB, 2);
            float iA = 1.f / sA, iB = 1.f / sB;
            #pragma unroll
            for (int nt = 0; nt < 8; nt++) {
                const int k0 = 8 * nt + 2 * q;
                float a00 = p0[2*nt] * iA, a01 = p0[2*nt+1] * iA;
                float a10 = p1[2*nt] * iB, a11 = p1[2*nt+1] * iB;
                *(uint32_t*)(smem + SM_AT + s0r * 144 + k0 * 2)       = bf2(a00, a01);
                *(uint32_t*)(smem + SM_AT + (s0r + 8) * 144 + k0 * 2) = bf2(a10, a11);
                // per-k partial sums over this warp's 16 s rows
                float v0 = a00 + a10, v1 = a01 + a11;
                v0 += __shfl_xor_sync(0xffffffffu, v0, 4);
                v1 += __shfl_xor_sync(0xffffffffu, v1, 4);
                v0 += __shfl_xor_sync(0xffffffffu, v0, 8);
                v1 += __shfl_xor_sync(0xffffffffu, v1, 8);
                v0 += __shfl_xor_sync(0xffffffffu, v0, 16);
                v1 += __shfl_xor_sync(0xffffffffu, v1, 16);
                if (g == 0) {
                    atp[w * 64 + k0]     = v0;
                    atp[w * 64 + k0 + 1] = v1;
                }
            }
        }
        __syncthreads();   // AT + atp ready

        if (tid < KDIM) {
            float a = 0.f;
            #pragma unroll
            for (int ww = 0; ww < 8; ww++) a += atp[ww * 64 + tid];
            aAcc += a;
        }

        // ---- GEMM2: e[c=128, k=64] += Xh . a ----
        {
            uint32_t aH[4], bb[2];
            #pragma unroll
            for (int kc = 0; kc < 8; kc++) {
                ldm4(aH, a2base + kc * 32);               // 16 s-elems * 2B
                #pragma unroll
                for (int nt = 0; nt < 8; nt++) {
                    ldm2t(bb, bat + kc * 2304 + nt * 16); // 16 s-rows*144B ; 8 k*2B
                    mma16816(acc2[nt], aH, bb);
                }
            }
        }
        __syncthreads();   // GEMM2 reads done before next tile's XT/AT rewrite
    }

    // ---- epilogue: write chunk partials ----
    {
        float* ep = g_epart + ((long)(chunk * BDIM + b) * KDIM) * CDIM;
        const int c0r = m0 + (lane >> 2), q = lane & 3;
        #pragma unroll
        for (int nt = 0; nt < 8; nt++) {
            int k0 = 8 * nt + 2 * q;
            ep[k0 * CDIM + c0r]           = acc2[nt][0];
            ep[(k0 + 1) * CDIM + c0r]     = acc2[nt][1];
            ep[k0 * CDIM + c0r + 8]       = acc2[nt][2];
            ep[(k0 + 1) * CDIM + c0r + 8] = acc2[nt][3];
        }
        if (tid < KDIM) g_Apart[(chunk * BDIM + b) * KDIM + tid] = aAcc;
    }
}

// ---------------------------------------------------------------------------
// Kernel B: reduce chunk partials, subtract A*cw, BN batch stats per k
// ---------------------------------------------------------------------------
__global__ void encnet_stats(const float* __restrict__ cw,
                             const float* __restrict__ bnw,
                             const float* __restrict__ bnb)
{
    const int k = blockIdx.x, tid = threadIdx.x;   // 256 threads
    __shared__ float Ab[BDIM];
    __shared__ float red[256];

    if (tid < BDIM) {
        float a = 0.f;
        #pragma unroll
        for (int ch = 0; ch < NCHUNK; ch++) a += g_Apart[(ch * BDIM + tid) * KDIM + k];
        Ab[tid] = a;
    }
    __syncthreads();

    float sum = 0.f, ss = 0.f;
    for (int i = tid; i < BDIM * CDIM; i += 256) {
        int bb = i >> 7, c = i & 127;
        float v = 0.f;
        #pragma unroll
        for (int ch = 0; ch < NCHUNK; ch++)
            v += g_epart[(((long)ch * BDIM + bb) * KDIM + k) * CDIM + c];
        v -= Ab[bb] * __ldg(cw + k * CDIM + c);
        g_ecorr[(bb * KDIM + k) * CDIM + c] = v;
        sum += v;
        ss = fmaf(v, v, ss);
    }
    red[tid] = sum; __syncthreads();
    for (int o = 128; o > 0; o >>= 1) { if (tid < o) red[tid] += red[tid + o]; __syncthreads(); }
    float tsum = red[0]; __syncthreads();
    red[tid] = ss; __syncthreads();
    for (int o = 128; o > 0; o >>= 1) { if (tid < o) red[tid] += red[tid + o]; __syncthreads(); }
    if (tid == 0) {
        const float n = (float)(BDIM * CDIM);
        float mean = tsum / n;
        float var = red[0] / n - mean * mean;
        float rstd = rsqrtf(var + 1e-5f);
        float g = rstd * __ldg(bnw + k);
        g_gk[k] = g;
        g_hk[k] = __ldg(bnb + k) - mean * g;
    }
}

// ---------------------------------------------------------------------------
// Kernel C: e_norm (mean of relu over k) + FC + sigmoid -> per-(b,c) scale
// ---------------------------------------------------------------------------
__global__ void encnet_fc(const float* __restrict__ fcw, const float* __restrict__ fcb)
{
    const int b = blockIdx.x, tid = threadIdx.x;   // 128 threads
    __shared__ float en[CDIM];
    float acc = 0.f;
    #pragma unroll 4
    for (int k = 0; k < KDIM; k++) {
        float v = g_ecorr[(b * KDIM + k) * CDIM + tid];
        acc += fmaxf(fmaf(v, g_gk[k], g_hk[k]), 0.f);
    }
    en[tid] = acc * (1.f / (float)KDIM);
    __syncthreads();

    float lg = __ldg(fcb + tid);
    const float* wr = fcw + tid * CDIM;
    #pragma unroll 4
    for (int c2 = 0; c2 < CDIM; c2++) lg = fmaf(en[c2], __ldg(wr + c2), lg);
    g_scale[b * CDIM + tid] = 1.f / (1.f + __expf(-lg));
}

// ---------------------------------------------------------------------------
// Kernel D: out = x * scale  (memory bound)
// ---------------------------------------------------------------------------
__global__ void encnet_scale(const float4* __restrict__ x4, float4* __restrict__ out4)
{
    const int total = (BDIM * CDIM * SEQ) / 4;
    for (int i = blockIdx.x * blockDim.x + threadIdx.x; i < total;
         i += gridDim.x * blockDim.x) {
        float s = __ldg(&g_scale[i >> 12]);
        float4 v = __ldg(x4 + i);
        v.x *= s; v.y *= s; v.z *= s; v.w *= s;
        out4[i] = v;
    }
}

// ---------------------------------------------------------------------------
extern "C" void kernel_launch(void* const* d_in, const int* in_sizes, int n_in,
                              void* d_out, int out_size)
{
    const float* x    = (const float*)d_in[0];
    const float* cw   = (const float*)d_in[1];
    const float* smth = (const float*)d_in[2];
    const float* bnw  = (const float*)d_in[3];
    const float* bnb  = (const float*)d_in[4];
    const float* fcw  = (const float*)d_in[5];
    const float* fcb  = (const float*)d_in[6];
    float* out = (float*)d_out;

    cudaFuncSetAttribute(encnet_main, cudaFuncAttributeMaxDynamicSharedMemorySize, SMEM_BYTES);

    encnet_main <<<dim3(NCHUNK, BDIM), TPB, SMEM_BYTES>>>(x, cw, smth);
    encnet_stats<<<KDIM, 256>>>(cw, bnw, bnb);
    encnet_fc   <<<BDIM, CDIM>>>(fcw, fcb);
    encnet_scale<<<4096, 256>>>((const float4*)x, (float4*)out);
}